// round 1
// baseline (speedup 1.0000x reference)
#include <cuda_runtime.h>
#include <cstdint>

#define KTOP 2048
#define DD 128
#define NBINS 65536
#define CAND_MAX 32768
#define NMAX 500224

// ---- static scratch (no allocations allowed) ----
__device__ unsigned int g_hist[NBINS];
__device__ float g_y[NMAX];
__device__ float g_norm;
__device__ unsigned int g_tbin;
__device__ unsigned int g_cnt;
__device__ unsigned long long g_cand[CAND_MAX];
__device__ float g_tval[KTOP];
__device__ int g_tidx[KTOP];

// monotonic unsigned key for f32 ordering
__device__ __forceinline__ unsigned int fkey(float f) {
    unsigned int u = __float_as_uint(f);
    return (u & 0x80000000u) ? ~u : (u | 0x80000000u);
}

// K0: zero histogram + counter, compute ||p||
__global__ void k0_init(const float* __restrict__ p) {
    int t = blockIdx.x * blockDim.x + threadIdx.x;
    if (t < NBINS) g_hist[t] = 0u;
    if (blockIdx.x == 0) {
        if (threadIdx.x == 0) g_cnt = 0u;
        if (threadIdx.x < 32) {
            int l = threadIdx.x;
            float a = p[l], b = p[l + 32], c = p[l + 64], d = p[l + 96];
            float s = a * a + b * b + c * c + d * d;
            #pragma unroll
            for (int o = 16; o; o >>= 1) s += __shfl_xor_sync(0xffffffffu, s, o);
            if (l == 0) g_norm = sqrtf(s);
        }
    }
}

// K1: warp-per-row dot product; store y; histogram top-16 key bits
__global__ void k1_dot(const float* __restrict__ x, const float* __restrict__ p, int n) {
    const int lane = threadIdx.x & 31;
    const int warp = (blockIdx.x * blockDim.x + threadIdx.x) >> 5;
    const int nwarps = (gridDim.x * blockDim.x) >> 5;
    const float4 pl = *reinterpret_cast<const float4*>(p + lane * 4);
    const float norm = g_norm;

    for (int r = warp; r < n; r += 2 * nwarps) {
        int r2 = r + nwarps;
        bool has2 = (r2 < n);
        float4 a = *reinterpret_cast<const float4*>(x + (size_t)r * DD + lane * 4);
        float4 b = make_float4(0.f, 0.f, 0.f, 0.f);
        if (has2) b = *reinterpret_cast<const float4*>(x + (size_t)r2 * DD + lane * 4);

        float sa = a.x * pl.x + a.y * pl.y + a.z * pl.z + a.w * pl.w;
        float sb = b.x * pl.x + b.y * pl.y + b.z * pl.z + b.w * pl.w;
        #pragma unroll
        for (int o = 16; o; o >>= 1) {
            sa += __shfl_xor_sync(0xffffffffu, sa, o);
            sb += __shfl_xor_sync(0xffffffffu, sb, o);
        }
        if (lane == 0) {
            float ya = sa / norm;
            g_y[r] = ya;
            atomicAdd(&g_hist[fkey(ya) >> 16], 1u);
            if (has2) {
                float yb = sb / norm;
                g_y[r2] = yb;
                atomicAdd(&g_hist[fkey(yb) >> 16], 1u);
            }
        }
    }
}

// K2: single-block suffix scan of histogram -> threshold bin
__global__ void k2_select() {
    __shared__ unsigned int suf[1024];
    int t = threadIdx.x;
    int base = t * 64;
    unsigned int part = 0;
    #pragma unroll 8
    for (int i = 0; i < 64; i++) part += g_hist[base + i];
    suf[t] = part;
    __syncthreads();
    #pragma unroll
    for (int off = 1; off < 1024; off <<= 1) {
        unsigned int v = (t + off < 1024) ? suf[t + off] : 0u;
        __syncthreads();
        suf[t] += v;
        __syncthreads();
    }
    unsigned int incl = suf[t];
    unsigned int excl = incl - part;
    if (excl < KTOP && incl >= KTOP) {
        unsigned int acc = excl;
        for (int b = base + 63; b >= base; b--) {
            acc += g_hist[b];
            if (acc >= KTOP) { g_tbin = (unsigned int)b; break; }
        }
    }
}

// K3: compact candidates >= threshold bin into packed 64-bit sort keys
__device__ __forceinline__ void try_push(float y, int i, unsigned int tb) {
    unsigned int key = fkey(y);
    if ((key >> 16) >= tb) {
        unsigned int pos = atomicAdd(&g_cnt, 1u);
        if (pos < CAND_MAX) {
            // value-descending major, index-ascending minor (~i so bigger = smaller idx)
            g_cand[pos] = ((unsigned long long)key << 32) | (unsigned long long)(~(unsigned int)i);
        }
    }
}

__global__ void k3_compact(int n) {
    unsigned int tb = g_tbin;
    int i4 = (blockIdx.x * blockDim.x + threadIdx.x) * 4;
    if (i4 + 3 < n) {
        float4 v = *reinterpret_cast<const float4*>(g_y + i4);
        try_push(v.x, i4 + 0, tb);
        try_push(v.y, i4 + 1, tb);
        try_push(v.z, i4 + 2, tb);
        try_push(v.w, i4 + 3, tb);
    } else if (i4 < n) {
        for (int j = i4; j < n; j++) try_push(g_y[j], j, tb);
    }
}

// K4: exact rank by counting; write sorted top-K (val, idx)
__global__ void k4_rank() {
    int C = (int)min(g_cnt, (unsigned int)CAND_MAX);
    int j = blockIdx.x * blockDim.x + threadIdx.x;
    if (j >= C) return;
    unsigned long long pk = g_cand[j];
    int rank = 0;
    int i = 0;
    for (; i + 4 <= C; i += 4) {
        rank += (g_cand[i + 0] > pk);
        rank += (g_cand[i + 1] > pk);
        rank += (g_cand[i + 2] > pk);
        rank += (g_cand[i + 3] > pk);
    }
    for (; i < C; i++) rank += (g_cand[i] > pk);
    if (rank < KTOP) {
        unsigned int key = (unsigned int)(pk >> 32);
        unsigned int u = (key & 0x80000000u) ? (key ^ 0x80000000u) : ~key;
        g_tval[rank] = __uint_as_float(u);
        g_tidx[rank] = (int)(~(unsigned int)(pk & 0xFFFFFFFFull));
    }
}

// K5: warp-per-row gather + tanh scale
__global__ void k5_gather(const float* __restrict__ x, float* __restrict__ out) {
    int w = (blockIdx.x * blockDim.x + threadIdx.x) >> 5;
    int lane = threadIdx.x & 31;
    if (w >= KTOP) return;
    int idx = g_tidx[w];
    float t = tanhf(g_tval[w]);
    float4 v = *reinterpret_cast<const float4*>(x + (size_t)idx * DD + lane * 4);
    float4 o = make_float4(v.x * t, v.y * t, v.z * t, v.w * t);
    *reinterpret_cast<float4*>(out + (size_t)w * DD + lane * 4) = o;
}

extern "C" void kernel_launch(void* const* d_in, const int* in_sizes, int n_in,
                              void* d_out, int out_size) {
    const float* x = (const float*)d_in[0];
    const float* p = (const float*)d_in[1];
    int n = in_sizes[0] / DD;

    k0_init<<<NBINS / 256, 256>>>(p);
    k1_dot<<<1184, 256>>>(x, p, n);
    k2_select<<<1, 1024>>>();
    k3_compact<<<(n + 1023) / 1024, 256>>>(n);
    k4_rank<<<CAND_MAX / 256, 256>>>();
    k5_gather<<<(KTOP * 32) / 256, 256>>>(x, (float*)d_out);
}

// round 2
// speedup vs baseline: 1.2994x; 1.2994x over previous
#include <cuda_runtime.h>
#include <cstdint>

#define KTOP 2048
#define DD 128
#define NBINS 65536
#define CAND_MAX 8192
#define NMAX 500224

// ---- static scratch (no allocations allowed) ----
__device__ unsigned int g_hist[NBINS];
__device__ float g_y[NMAX];
__device__ float g_pn[DD];              // p / ||p||
__device__ unsigned int g_tbin;
__device__ unsigned int g_cnt;
__device__ __align__(16) unsigned long long g_cand[CAND_MAX];
__device__ float g_tval[KTOP];
__device__ int g_tidx[KTOP];

// monotonic unsigned key for f32 ordering
__device__ __forceinline__ unsigned int fkey(float f) {
    unsigned int u = __float_as_uint(f);
    return (u & 0x80000000u) ? ~u : (u | 0x80000000u);
}

// K0: zero histogram + counter; compute pn = p/||p||
__global__ void k0_init(const float* __restrict__ p) {
    int t = blockIdx.x * blockDim.x + threadIdx.x;   // 16384 threads
    uint4 z = make_uint4(0u, 0u, 0u, 0u);
    reinterpret_cast<uint4*>(g_hist)[t] = z;
    if (t == 0) g_cnt = 0u;
    if (blockIdx.x == 0 && threadIdx.x < 32) {
        int l = threadIdx.x;
        float4 pl = reinterpret_cast<const float4*>(p)[l];
        float s = pl.x * pl.x + pl.y * pl.y + pl.z * pl.z + pl.w * pl.w;
        #pragma unroll
        for (int o = 16; o; o >>= 1) s += __shfl_xor_sync(0xffffffffu, s, o);
        float inv = rsqrtf(s) * (sqrtf(s) * rsqrtf(s));   // refine? keep simple:
        inv = 1.0f / sqrtf(s);
        float4 o4 = make_float4(pl.x * inv, pl.y * inv, pl.z * inv, pl.w * inv);
        reinterpret_cast<float4*>(g_pn)[l] = o4;
    }
}

// K1: thread-per-row dot product with pn staged in smem; store y; histogram
__global__ void __launch_bounds__(256) k1_dot(const float* __restrict__ x, int n) {
    __shared__ float4 ps[32];
    if (threadIdx.x < 32)
        ps[threadIdx.x] = reinterpret_cast<const float4*>(g_pn)[threadIdx.x];
    __syncthreads();

    int r = blockIdx.x * blockDim.x + threadIdx.x;
    if (r >= n) return;

    const float4* __restrict__ xr =
        reinterpret_cast<const float4*>(x + (size_t)r * DD);

    float a0 = 0.f, a1 = 0.f, a2 = 0.f, a3 = 0.f;
    #pragma unroll
    for (int j = 0; j < 32; j += 4) {
        float4 v0 = xr[j + 0];
        float4 v1 = xr[j + 1];
        float4 v2 = xr[j + 2];
        float4 v3 = xr[j + 3];
        float4 p0 = ps[j + 0];
        float4 p1 = ps[j + 1];
        float4 p2 = ps[j + 2];
        float4 p3 = ps[j + 3];
        a0 += v0.x * p0.x + v0.y * p0.y + v0.z * p0.z + v0.w * p0.w;
        a1 += v1.x * p1.x + v1.y * p1.y + v1.z * p1.z + v1.w * p1.w;
        a2 += v2.x * p2.x + v2.y * p2.y + v2.z * p2.z + v2.w * p2.w;
        a3 += v3.x * p3.x + v3.y * p3.y + v3.z * p3.z + v3.w * p3.w;
    }
    float y = (a0 + a1) + (a2 + a3);
    g_y[r] = y;
    atomicAdd(&g_hist[fkey(y) >> 16], 1u);
}

// K2: single-block suffix scan of histogram -> threshold bin
__global__ void k2_select() {
    __shared__ unsigned int suf[1024];
    int t = threadIdx.x;
    int base = t * 64;
    unsigned int part = 0;
    const uint4* h4 = reinterpret_cast<const uint4*>(g_hist + base);
    #pragma unroll
    for (int i = 0; i < 16; i++) {
        uint4 v = h4[i];
        part += v.x + v.y + v.z + v.w;
    }
    suf[t] = part;
    __syncthreads();
    #pragma unroll
    for (int off = 1; off < 1024; off <<= 1) {
        unsigned int v = (t + off < 1024) ? suf[t + off] : 0u;
        __syncthreads();
        suf[t] += v;
        __syncthreads();
    }
    unsigned int incl = suf[t];
    unsigned int excl = incl - part;
    if (excl < KTOP && incl >= KTOP) {
        unsigned int acc = excl;
        for (int b = base + 63; b >= base; b--) {
            acc += g_hist[b];
            if (acc >= KTOP) { g_tbin = (unsigned int)b; break; }
        }
    }
}

// K3: compact candidates >= threshold bin into packed 64-bit sort keys
__device__ __forceinline__ void try_push(float y, int i, unsigned int tb) {
    unsigned int key = fkey(y);
    if ((key >> 16) >= tb) {
        unsigned int pos = atomicAdd(&g_cnt, 1u);
        if (pos < CAND_MAX) {
            // value-descending major, index-ascending minor (~i so bigger = smaller idx)
            g_cand[pos] = ((unsigned long long)key << 32) | (unsigned long long)(~(unsigned int)i);
        }
    }
}

__global__ void __launch_bounds__(256) k3_compact(int n) {
    unsigned int tb = g_tbin;
    int i4 = (blockIdx.x * blockDim.x + threadIdx.x) * 4;
    if (i4 + 3 < n) {
        float4 v = *reinterpret_cast<const float4*>(g_y + i4);
        try_push(v.x, i4 + 0, tb);
        try_push(v.y, i4 + 1, tb);
        try_push(v.z, i4 + 2, tb);
        try_push(v.w, i4 + 3, tb);
    } else if (i4 < n) {
        for (int j = i4; j < n; j++) try_push(g_y[j], j, tb);
    }
}

// K4: exact rank by counting; 32-thread blocks spread across SMs,
// vectorized ulonglong2 loads (8 keys / iter).
__global__ void __launch_bounds__(32) k4_rank() {
    int C = (int)min(g_cnt, (unsigned int)CAND_MAX);
    if (blockIdx.x * 32 >= C) return;      // whole-block early exit
    int j = blockIdx.x * 32 + threadIdx.x;
    unsigned long long pk = (j < C) ? g_cand[j] : 0ull;

    int rank = 0;
    const ulonglong2* c2 = reinterpret_cast<const ulonglong2*>(g_cand);
    int i = 0;
    for (; i + 8 <= C; i += 8) {
        ulonglong2 v0 = c2[(i >> 1) + 0];
        ulonglong2 v1 = c2[(i >> 1) + 1];
        ulonglong2 v2 = c2[(i >> 1) + 2];
        ulonglong2 v3 = c2[(i >> 1) + 3];
        rank += (v0.x > pk) + (v0.y > pk);
        rank += (v1.x > pk) + (v1.y > pk);
        rank += (v2.x > pk) + (v2.y > pk);
        rank += (v3.x > pk) + (v3.y > pk);
    }
    for (; i < C; i++) rank += (g_cand[i] > pk);

    if (j < C && rank < KTOP) {
        unsigned int key = (unsigned int)(pk >> 32);
        unsigned int u = (key & 0x80000000u) ? (key ^ 0x80000000u) : ~key;
        g_tval[rank] = __uint_as_float(u);
        g_tidx[rank] = (int)(~(unsigned int)(pk & 0xFFFFFFFFull));
    }
}

// K5: warp-per-row gather + tanh scale
__global__ void __launch_bounds__(256) k5_gather(const float* __restrict__ x,
                                                 float* __restrict__ out) {
    int w = (blockIdx.x * blockDim.x + threadIdx.x) >> 5;
    int lane = threadIdx.x & 31;
    if (w >= KTOP) return;
    int idx = g_tidx[w];
    float t = tanhf(g_tval[w]);
    float4 v = *reinterpret_cast<const float4*>(x + (size_t)idx * DD + lane * 4);
    float4 o = make_float4(v.x * t, v.y * t, v.z * t, v.w * t);
    *reinterpret_cast<float4*>(out + (size_t)w * DD + lane * 4) = o;
}

extern "C" void kernel_launch(void* const* d_in, const int* in_sizes, int n_in,
                              void* d_out, int out_size) {
    const float* x = (const float*)d_in[0];
    const float* p = (const float*)d_in[1];
    int n = in_sizes[0] / DD;

    k0_init<<<128, 128>>>(p);                       // 16384 threads: hist zero + pn
    k1_dot<<<(n + 255) / 256, 256>>>(x, n);
    k2_select<<<1, 1024>>>();
    k3_compact<<<(n + 1023) / 1024, 256>>>(n);
    k4_rank<<<CAND_MAX / 32, 32>>>();
    k5_gather<<<(KTOP * 32) / 256, 256>>>(x, (float*)d_out);
}

// round 3
// speedup vs baseline: 1.3941x; 1.0729x over previous
#include <cuda_runtime.h>
#include <cstdint>

#define KTOP 2048
#define DD 128
#define NBINS 65536
#define CAND_MAX 8192
#define NMAX 500224

// ---- static scratch (no allocations allowed) ----
__device__ unsigned int g_hist[NBINS];
__device__ float g_y[NMAX];
__device__ float g_pn[DD];              // p / ||p||
__device__ unsigned int g_tbin;
__device__ unsigned int g_cnt;
__device__ __align__(16) unsigned long long g_cand[CAND_MAX];
__device__ float g_tval[KTOP];
__device__ int g_tidx[KTOP];

// monotonic unsigned key for f32 ordering
__device__ __forceinline__ unsigned int fkey(float f) {
    unsigned int u = __float_as_uint(f);
    return (u & 0x80000000u) ? ~u : (u | 0x80000000u);
}

__device__ __forceinline__ float dot4(float4 a, float4 b) {
    return a.x * b.x + a.y * b.y + a.z * b.z + a.w * b.w;
}

// K0: zero histogram + counter; compute pn = p/||p||
__global__ void k0_init(const float* __restrict__ p) {
    int t = blockIdx.x * blockDim.x + threadIdx.x;   // 16384 threads
    reinterpret_cast<uint4*>(g_hist)[t] = make_uint4(0u, 0u, 0u, 0u);
    if (t == 0) g_cnt = 0u;
    if (blockIdx.x == 0 && threadIdx.x < 32) {
        int l = threadIdx.x;
        float4 pl = reinterpret_cast<const float4*>(p)[l];
        float s = pl.x * pl.x + pl.y * pl.y + pl.z * pl.z + pl.w * pl.w;
        #pragma unroll
        for (int o = 16; o; o >>= 1) s += __shfl_xor_sync(0xffffffffu, s, o);
        float inv = 1.0f / sqrtf(s);
        reinterpret_cast<float4*>(g_pn)[l] =
            make_float4(pl.x * inv, pl.y * inv, pl.z * inv, pl.w * inv);
    }
}

// K1: 8-lanes-per-row, 8 rows per warp per launch.
// Coalesced: load i covers one full 128B line per row (4 wavefronts/instr).
// p slice lives in 16 registers; reduction = 3 SHFL per 4 rows.
__global__ void __launch_bounds__(256) k1_dot(const float* __restrict__ x, int n) {
    const int lane = threadIdx.x & 31;
    const int l8 = lane & 7;
    const int g = lane >> 3;
    const int warp = (blockIdx.x * blockDim.x + threadIdx.x) >> 5;

    const float4* __restrict__ pn4 = reinterpret_cast<const float4*>(g_pn);
    float4 p0 = pn4[l8 + 0];
    float4 p1 = pn4[l8 + 8];
    float4 p2 = pn4[l8 + 16];
    float4 p3 = pn4[l8 + 24];

    const float4* __restrict__ x4 = reinterpret_cast<const float4*>(x);
    int rA = warp * 8 + g;      // rows rA (group pass 1) and rA+4 (pass 2)
    int rB = rA + 4;
    bool hA = rA < n, hB = rB < n;

    float4 z = make_float4(0.f, 0.f, 0.f, 0.f);
    float4 a0 = z, a1 = z, a2 = z, a3 = z;
    float4 b0 = z, b1 = z, b2 = z, b3 = z;
    if (hA) {
        const float4* xa = x4 + (size_t)rA * 32 + l8;
        a0 = xa[0]; a1 = xa[8]; a2 = xa[16]; a3 = xa[24];
    }
    if (hB) {
        const float4* xb = x4 + (size_t)rB * 32 + l8;
        b0 = xb[0]; b1 = xb[8]; b2 = xb[16]; b3 = xb[24];
    }

    float sA = (dot4(a0, p0) + dot4(a1, p1)) + (dot4(a2, p2) + dot4(a3, p3));
    float sB = (dot4(b0, p0) + dot4(b1, p1)) + (dot4(b2, p2) + dot4(b3, p3));

    #pragma unroll
    for (int o = 4; o; o >>= 1) {
        sA += __shfl_xor_sync(0xffffffffu, sA, o);
        sB += __shfl_xor_sync(0xffffffffu, sB, o);
    }

    if (l8 == 0) {
        if (hA) {
            g_y[rA] = sA;
            atomicAdd(&g_hist[fkey(sA) >> 16], 1u);
        }
        if (hB) {
            g_y[rB] = sB;
            atomicAdd(&g_hist[fkey(sB) >> 16], 1u);
        }
    }
}

// K2: single-block suffix scan of histogram -> threshold bin
__global__ void k2_select() {
    __shared__ unsigned int suf[1024];
    int t = threadIdx.x;
    int base = t * 64;
    unsigned int part = 0;
    const uint4* h4 = reinterpret_cast<const uint4*>(g_hist + base);
    #pragma unroll
    for (int i = 0; i < 16; i++) {
        uint4 v = h4[i];
        part += v.x + v.y + v.z + v.w;
    }
    suf[t] = part;
    __syncthreads();
    #pragma unroll
    for (int off = 1; off < 1024; off <<= 1) {
        unsigned int v = (t + off < 1024) ? suf[t + off] : 0u;
        __syncthreads();
        suf[t] += v;
        __syncthreads();
    }
    unsigned int incl = suf[t];
    unsigned int excl = incl - part;
    if (excl < KTOP && incl >= KTOP) {
        unsigned int acc = excl;
        for (int b = base + 63; b >= base; b--) {
            acc += g_hist[b];
            if (acc >= KTOP) { g_tbin = (unsigned int)b; break; }
        }
    }
}

// K3: compact candidates >= threshold bin into packed 64-bit sort keys.
// Two front-batched independent float4 loads per thread (MLP=2, one shot).
__device__ __forceinline__ void try_push(float y, int i, unsigned int tb) {
    unsigned int key = fkey(y);
    if ((key >> 16) >= tb) {
        unsigned int pos = atomicAdd(&g_cnt, 1u);
        if (pos < CAND_MAX) {
            // value-descending major, index-ascending minor (~i so bigger = smaller idx)
            g_cand[pos] = ((unsigned long long)key << 32) | (unsigned long long)(~(unsigned int)i);
        }
    }
}

#define K3_THREADS 62720   // 245 blocks * 256
__global__ void __launch_bounds__(256) k3_compact(int n) {
    unsigned int tb = g_tbin;
    int t = blockIdx.x * blockDim.x + threadIdx.x;
    int n4 = n >> 2;
    const float4* y4 = reinterpret_cast<const float4*>(g_y);
    int i0 = t, i1 = t + K3_THREADS;
    float4 v0 = make_float4(0.f, 0.f, 0.f, 0.f), v1 = v0;
    bool h0 = i0 < n4, h1 = i1 < n4;
    if (h0) v0 = y4[i0];
    if (h1) v1 = y4[i1];
    if (h0) {
        try_push(v0.x, i0 * 4 + 0, tb);
        try_push(v0.y, i0 * 4 + 1, tb);
        try_push(v0.z, i0 * 4 + 2, tb);
        try_push(v0.w, i0 * 4 + 3, tb);
    }
    if (h1) {
        try_push(v1.x, i1 * 4 + 0, tb);
        try_push(v1.y, i1 * 4 + 1, tb);
        try_push(v1.z, i1 * 4 + 2, tb);
        try_push(v1.w, i1 * 4 + 3, tb);
    }
    if (t == 0) {                       // n % 4 tail
        for (int j = n & ~3; j < n; j++) try_push(g_y[j], j, tb);
    }
}

// K4: exact rank by counting; 32-thread blocks spread across SMs,
// vectorized ulonglong2 loads (8 keys / iter).
__global__ void __launch_bounds__(32) k4_rank() {
    int C = (int)min(g_cnt, (unsigned int)CAND_MAX);
    if (blockIdx.x * 32 >= C) return;      // whole-block early exit
    int j = blockIdx.x * 32 + threadIdx.x;
    unsigned long long pk = (j < C) ? g_cand[j] : 0ull;

    int rank = 0;
    const ulonglong2* c2 = reinterpret_cast<const ulonglong2*>(g_cand);
    int i = 0;
    for (; i + 8 <= C; i += 8) {
        ulonglong2 v0 = c2[(i >> 1) + 0];
        ulonglong2 v1 = c2[(i >> 1) + 1];
        ulonglong2 v2 = c2[(i >> 1) + 2];
        ulonglong2 v3 = c2[(i >> 1) + 3];
        rank += (v0.x > pk) + (v0.y > pk);
        rank += (v1.x > pk) + (v1.y > pk);
        rank += (v2.x > pk) + (v2.y > pk);
        rank += (v3.x > pk) + (v3.y > pk);
    }
    for (; i < C; i++) rank += (g_cand[i] > pk);

    if (j < C && rank < KTOP) {
        unsigned int key = (unsigned int)(pk >> 32);
        unsigned int u = (key & 0x80000000u) ? (key ^ 0x80000000u) : ~key;
        g_tval[rank] = __uint_as_float(u);
        g_tidx[rank] = (int)(~(unsigned int)(pk & 0xFFFFFFFFull));
    }
}

// K5: warp-per-row gather + tanh scale
__global__ void __launch_bounds__(256) k5_gather(const float* __restrict__ x,
                                                 float* __restrict__ out) {
    int w = (blockIdx.x * blockDim.x + threadIdx.x) >> 5;
    int lane = threadIdx.x & 31;
    if (w >= KTOP) return;
    int idx = g_tidx[w];
    float t = tanhf(g_tval[w]);
    float4 v = *reinterpret_cast<const float4*>(x + (size_t)idx * DD + lane * 4);
    float4 o = make_float4(v.x * t, v.y * t, v.z * t, v.w * t);
    *reinterpret_cast<float4*>(out + (size_t)w * DD + lane * 4) = o;
}

extern "C" void kernel_launch(void* const* d_in, const int* in_sizes, int n_in,
                              void* d_out, int out_size) {
    const float* x = (const float*)d_in[0];
    const float* p = (const float*)d_in[1];
    int n = in_sizes[0] / DD;

    int warps = (n + 7) / 8;                       // 8 rows per warp
    int k1_blocks = (warps + 7) / 8;               // 8 warps per block

    k0_init<<<128, 128>>>(p);
    k1_dot<<<k1_blocks, 256>>>(x, n);
    k2_select<<<1, 1024>>>();
    k3_compact<<<245, 256>>>(n);
    k4_rank<<<CAND_MAX / 32, 32>>>();
    k5_gather<<<(KTOP * 32) / 256, 256>>>(x, (float*)d_out);
}